// round 13
// baseline (speedup 1.0000x reference)
#include <cuda_runtime.h>
#include <cuda_bf16.h>

// Fixed shapes
#define BB 8
#define CC 8
#define HH 512
#define WW 1024
#define HWSZ (HH * WW)

// Tiling: 32x8 threads; each thread owns 16 pixels = 4 adjacent rows x 4 cols
#define BX 32
#define BY 8
#define TW (BX * 4)        // tile width 128 px
#define TH 32              // tile height 32 px (4 rows per thread)
#define NWARPS 8
#define NBLOCKS ((WW / TW) * (HH / TH) * BB)   // 1024

#define HROWS (TH + 4)     // 36
#define HU 34              // uints per halo row (136 bytes: cols gx0-4 .. gx0+131)
#define HTOT (HROWS * HU)  // 1224 uints

__device__ double g_acc[BB][26];   // zeroed at module load; last block re-zeroes
__device__ unsigned g_ticket;

#define CP(v, p) ((p) == 0 ? (v).x : (p) == 1 ? (v).y : (p) == 2 ? (v).z : (v).w)

__device__ __forceinline__ unsigned hwin_max(unsigned l, unsigned m, unsigned h) {
    return __vmaxs4(__vmaxs4(__byte_perm(l, m, 0x5432), __byte_perm(l, m, 0x6543)),
           __vmaxs4(m, __vmaxs4(__byte_perm(m, h, 0x4321), __byte_perm(m, h, 0x5432))));
}
__device__ __forceinline__ unsigned hwin_min(unsigned l, unsigned m, unsigned h) {
    return __vminu4(__vminu4(__byte_perm(l, m, 0x5432), __byte_perm(l, m, 0x6543)),
           __vminu4(m, __vminu4(__byte_perm(m, h, 0x4321), __byte_perm(m, h, 0x5432))));
}

__global__ __launch_bounds__(256, 4) void loss_main_kernel(
    const float* __restrict__ pred, const int* __restrict__ target,
    float* __restrict__ out)
{
    __shared__ __align__(16) unsigned s_t[HTOT];        // packed byte labels
    __shared__ float s_red[17][33];                     // padded (bank-conflict-free)
    __shared__ unsigned s_cnt[2][32];
    __shared__ float s_fin[2];
    __shared__ int s_last;

    const int b   = blockIdx.z;
    const int gx0 = blockIdx.x * TW;
    const int gy0 = blockIdx.y * TH;
    const int tx  = threadIdx.x;
    const int ty  = threadIdx.y;
    const int tid = ty * BX + tx;

    // ---- HOISTED row-0 pred loads: 8 independent LDG.128 first; consumed
    //      after staging + sync + morphology (covers DRAM latency) ----
    const int gy = gy0 + 4 * ty;          // first of 4 rows
    const int gx = gx0 + tx * 4;
    const float* pb = pred + (size_t)b * CC * HWSZ + (size_t)gy * WW + gx;
    float4 X[CC];
#pragma unroll
    for (int c = 0; c < CC; c++) X[c] = __ldcs((const float4*)(pb + (size_t)c * HWSZ));

    // ---- stage target halo as packed bytes: int4 load + PRMT pack ----
    // uint j of halo row covers cols gx0-4+4j .. +3; OOB uint -> 0xFFFFFFFF
    {
        const int* tgt_b = target + b * HWSZ;
#pragma unroll
        for (int k = 0; k < 5; k++) {
            int idx = tid + k * 256;
            if (idx < HTOT) {
                int row = idx / HU;
                int j   = idx - row * HU;
                int gyy = gy0 + row - 2;
                int cb  = gx0 - 4 + 4 * j;
                unsigned u = 0xFFFFFFFFu;
                if (gyy >= 0 && gyy < HH && cb >= 0 && cb < WW) {
                    int4 w = *(const int4*)(tgt_b + gyy * WW + cb);   // 16B-aligned
                    unsigned lo = __byte_perm((unsigned)w.x, (unsigned)w.y, 0x4040);
                    unsigned hi = __byte_perm((unsigned)w.z, (unsigned)w.w, 0x4040);
                    u = __byte_perm(lo, hi, 0x5410);
                }
                s_t[idx] = u;
            }
        }
    }
    __syncthreads();

    // ---- SIMD byte morphology for 4 adjacent rows (shared vertical chains) ----
    // pixel row r = 4ty+j sits at halo row r+2; window = halo rows (4ty+j)..(4ty+j+4).
    // Relative halo rows needed: 0..7. Full-width rows: 1..6 (a,b,c); rows 0,7: b only.
    unsigned tpk[4], dpk[4];
    {
        const int hb = (4 * ty) * HU + tx;
        unsigned r0b = s_t[hb + 1];
        unsigned r1a = s_t[hb + 1*HU], r1b = s_t[hb + 1*HU + 1], r1c = s_t[hb + 1*HU + 2];
        unsigned r2a = s_t[hb + 2*HU], r2b = s_t[hb + 2*HU + 1], r2c = s_t[hb + 2*HU + 2];
        unsigned r3a = s_t[hb + 3*HU], r3b = s_t[hb + 3*HU + 1], r3c = s_t[hb + 3*HU + 2];
        unsigned r4a = s_t[hb + 4*HU], r4b = s_t[hb + 4*HU + 1], r4c = s_t[hb + 4*HU + 2];
        unsigned r5a = s_t[hb + 5*HU], r5b = s_t[hb + 5*HU + 1], r5c = s_t[hb + 5*HU + 2];
        unsigned r6a = s_t[hb + 6*HU], r6b = s_t[hb + 6*HU + 1], r6c = s_t[hb + 6*HU + 2];
        unsigned r7b = s_t[hb + 7*HU + 1];

        // shared vertical pair chains (per column)
        unsigned p23a = __vmaxs4(r2a, r3a), p23b = __vmaxs4(r2b, r3b), p23c = __vmaxs4(r2c, r3c);
        unsigned p45a = __vmaxs4(r4a, r5a), p45b = __vmaxs4(r4b, r5b), p45c = __vmaxs4(r4c, r5c);
        unsigned q23a = __vminu4(r2a, r3a), q23b = __vminu4(r2b, r3b), q23c = __vminu4(r2c, r3c);
        unsigned q45a = __vminu4(r4a, r5a), q45b = __vminu4(r4b, r5b), q45c = __vminu4(r4c, r5c);

        // j=0: rows 1..3 ; j=1: rows 2..4 ; j=2: rows 3..5 ; j=3: rows 4..6
        unsigned mx, mn;

        mx = __vmaxs4(hwin_max(__vmaxs4(r1a, p23a), __vmaxs4(r1b, p23b), __vmaxs4(r1c, p23c)),
                      __vmaxs4(r0b, r4b));
        mn = __vminu4(hwin_min(__vminu4(r1a, q23a), __vminu4(r1b, q23b), __vminu4(r1c, q23c)),
                      __vminu4(r0b, r4b));
        tpk[0] = r2b;  dpk[0] = mx ^ mn;

        mx = __vmaxs4(hwin_max(__vmaxs4(p23a, r4a), __vmaxs4(p23b, r4b), __vmaxs4(p23c, r4c)),
                      __vmaxs4(r1b, r5b));
        mn = __vminu4(hwin_min(__vminu4(q23a, r4a), __vminu4(q23b, r4b), __vminu4(q23c, r4c)),
                      __vminu4(r1b, r5b));
        tpk[1] = r3b;  dpk[1] = mx ^ mn;

        mx = __vmaxs4(hwin_max(__vmaxs4(r3a, p45a), __vmaxs4(r3b, p45b), __vmaxs4(r3c, p45c)),
                      __vmaxs4(r2b, r6b));
        mn = __vminu4(hwin_min(__vminu4(r3a, q45a), __vminu4(r3b, q45b), __vminu4(r3c, q45c)),
                      __vminu4(r2b, r6b));
        tpk[2] = r4b;  dpk[2] = mx ^ mn;

        mx = __vmaxs4(hwin_max(__vmaxs4(p45a, r6a), __vmaxs4(p45b, r6b), __vmaxs4(p45c, r6c)),
                      __vmaxs4(r3b, r7b));
        mn = __vminu4(hwin_min(__vminu4(q45a, r6a), __vminu4(q45b, r6b), __vminu4(q45c, r6c)),
                      __vminu4(r3b, r7b));
        tpk[3] = r5b;  dpk[3] = mx ^ mn;
    }

    float sump[CC], inter[CC];
    unsigned cntA = 0, cntB = 0;               // classes 0-3 / 4-7, 8-bit fields (max 16/thread)
#pragma unroll
    for (int c = 0; c < CC; c++) { sump[c] = 0.f; inter[c] = 0.f; }
    float cw_s = 0.f;                          // ce*(1+2w), w in {1,10} -> 3 or 21

    auto proc_row = [&](unsigned t_packed, unsigned d) {
#pragma unroll
        for (int p = 0; p < 4; p++) {
            const unsigned tp = __byte_perm(t_packed, 0u, 0x4440u | p);
            const unsigned db = __byte_perm(d, 0u, 0x4440u | p);

            // exp WITHOUT max-subtraction: inputs N(0,1), |x| < ~6, no overflow
            float e[CC];
#pragma unroll
            for (int c = 0; c < CC; c++) e[c] = __expf(CP(X[c], p));
            float se = ((e[0] + e[1]) + (e[2] + e[3])) + ((e[4] + e[5]) + (e[6] + e[7]));
            float inv = __fdividef(1.0f, se);

            float xt = CP(X[0], p);
#pragma unroll
            for (int c = 1; c < CC; c++) xt = (tp == (unsigned)c) ? CP(X[c], p) : xt;
            const float ce = __logf(se) - xt;

#pragma unroll
            for (int c = 0; c < CC; c++) {
                sump[c] = fmaf(e[c], inv, sump[c]);
                if (tp == (unsigned)c) inter[c] = fmaf(e[c], inv, inter[c]);
            }

            cw_s = fmaf(db ? 21.0f : 3.0f, ce, cw_s);

            unsigned inc = 1u << ((tp & 3u) * 8);
            cntA += (tp < 4u) ? inc : 0u;
            cntB += (tp < 4u) ? 0u : inc;
        }
    };

#pragma unroll
    for (int j = 0; j < 4; j++) {
        proc_row(tpk[j], dpk[j]);
        if (j < 3) {
#pragma unroll
            for (int c = 0; c < CC; c++)        // next row into same regs
                X[c] = __ldcs((const float4*)(pb + (size_t)c * HWSZ + (size_t)(j + 1) * WW));
        }
    }

    // ---- block reduction: 3 shuffle levels (lanes 0-3 hold partials) ----
    const int lane = tid & 31;
    const int warp = tid >> 5;
    {
        float q[17];
#pragma unroll
        for (int c = 0; c < CC; c++) { q[c] = sump[c]; q[8 + c] = inter[c]; }
        q[16] = cw_s;
#pragma unroll
        for (int k = 0; k < 17; k++) {
            float v = q[k];
            v += __shfl_down_sync(0xFFFFFFFFu, v, 16);
            v += __shfl_down_sync(0xFFFFFFFFu, v, 8);
            v += __shfl_down_sync(0xFFFFFFFFu, v, 4);
            if (lane < 4) s_red[k][warp * 4 + lane] = v;
        }
        // counts: REDUX in 8-lane groups (8-bit fields, max 16*8=128, no overflow)
        const unsigned gmask = 0xFFu << ((lane >> 3) * 8);
        unsigned ua = __reduce_add_sync(gmask, cntA);
        unsigned ub = __reduce_add_sync(gmask, cntB);
        if ((lane & 7) == 0) {
            s_cnt[0][warp * 4 + (lane >> 3)] = ua;
            s_cnt[1][warp * 4 + (lane >> 3)] = ub;
        }
    }
    __syncthreads();

    if (tid < 17) {
        float s = 0.f;
#pragma unroll
        for (int w = 0; w < 32; w++) s += s_red[tid][w];
        int gi = (tid < 16) ? tid : 24;
        atomicAdd(&g_acc[b][gi], (double)s);
    }
    if (tid >= 32 && tid < 40) {
        int c = tid - 32;
        unsigned s = 0;
#pragma unroll
        for (int w = 0; w < 32; w++)
            s += (s_cnt[c >> 2][w] >> ((c & 3) * 8)) & 0xFFu;
        atomicAdd(&g_acc[b][16 + c], (double)s);
    }

    // ---- last-block finalize ----
    __syncthreads();
    if (tid == 0) {
        __threadfence();
        unsigned r = atomicAdd(&g_ticket, 1u);
        s_last = (r == NBLOCKS - 1);
        s_fin[0] = 0.f; s_fin[1] = 0.f;
    }
    __syncthreads();
    if (!s_last) return;
    __threadfence();

    float dterm = 0.f;
    if (tid < BB * CC) {
        int bb = tid >> 3, cc = tid & 7;
        float it   = (float)g_acc[bb][8 + cc];
        float card = (float)(g_acc[bb][cc] + g_acc[bb][16 + cc]);
        dterm = (2.0f * it + 1e-6f) / (card + 1e-6f);
    }
#pragma unroll
    for (int off = 16; off > 0; off >>= 1)
        dterm += __shfl_down_sync(0xFFFFFFFFu, dterm, off);
    if (lane == 0 && warp < 2) atomicAdd(&s_fin[0], dterm);
    if (tid < BB) atomicAdd(&s_fin[1], (float)g_acc[tid][24]);
    __syncthreads();

    if (tid == 0) {
        const float N = (float)BB * HH * WW;
        float dice = 1.0f - s_fin[0] / (float)(BB * CC);
        out[0] = s_fin[1] / N + 3.0f * dice;
    }
    if (tid < BB * 26) ((double*)g_acc)[tid] = 0.0;
    if (tid == 0) g_ticket = 0u;
}

extern "C" void kernel_launch(void* const* d_in, const int* in_sizes, int n_in,
                              void* d_out, int out_size)
{
    const float* pred   = (const float*)d_in[0];
    const int*   target = (const int*)d_in[1];
    float* out = (float*)d_out;

    dim3 block(BX, BY, 1);
    dim3 grid(WW / TW, HH / TH, BB);
    loss_main_kernel<<<grid, block>>>(pred, target, out);
}

// round 14
// speedup vs baseline: 1.1462x; 1.1462x over previous
#include <cuda_runtime.h>
#include <cuda_bf16.h>

// Fixed shapes
#define BB 8
#define CC 8
#define HH 512
#define WW 1024
#define HWSZ (HH * WW)

// Tiling: 32x8 threads; each thread owns 8 pixels = 2 adjacent rows x 4 cols
#define BX 32
#define BY 8
#define TW (BX * 4)        // tile width 128 px
#define TH 16              // tile height 16 px (2 rows per thread)
#define NWARPS 8
#define NBLOCKS ((WW / TW) * (HH / TH) * BB)   // 2048

#define HROWS (TH + 4)     // 20
#define HU 34              // uints per halo row (136 bytes: cols gx0-4 .. gx0+131)
#define HTOT (HROWS * HU)  // 680 uints

__device__ double g_acc[BB][26];   // zeroed at module load; last block re-zeroes
__device__ unsigned g_ticket;

#define CP(v, p) ((p) == 0 ? (v).x : (p) == 1 ? (v).y : (p) == 2 ? (v).z : (v).w)

__device__ __forceinline__ unsigned hwin_max(unsigned l, unsigned m, unsigned h) {
    return __vmaxs4(__vmaxs4(__byte_perm(l, m, 0x5432), __byte_perm(l, m, 0x6543)),
           __vmaxs4(m, __vmaxs4(__byte_perm(m, h, 0x4321), __byte_perm(m, h, 0x5432))));
}
__device__ __forceinline__ unsigned hwin_min(unsigned l, unsigned m, unsigned h) {
    return __vminu4(__vminu4(__byte_perm(l, m, 0x5432), __byte_perm(l, m, 0x6543)),
           __vminu4(m, __vminu4(__byte_perm(m, h, 0x4321), __byte_perm(m, h, 0x5432))));
}

__global__ __launch_bounds__(256, 4) void loss_main_kernel(
    const float* __restrict__ pred, const int* __restrict__ target,
    float* __restrict__ out)
{
    __shared__ __align__(16) float4 s_pb[CC][BX * BY];  // row-B prefetch (32 KB)
    __shared__ __align__(16) unsigned s_t[HTOT];        // packed byte labels
    __shared__ float s_red[17][33];                     // padded (bank-conflict-free)
    __shared__ unsigned s_cnt[2][16];
    __shared__ float s_fin[2];
    __shared__ int s_last;

    const int b   = blockIdx.z;
    const int gx0 = blockIdx.x * TW;
    const int gy0 = blockIdx.y * TH;
    const int tx  = threadIdx.x;
    const int ty  = threadIdx.y;
    const int tid = ty * BX + tx;

    // ---- HOISTED row-A pred loads: 8 independent LDG.128 first ----
    const int gy = gy0 + 2 * ty;          // row A; row B = gy+1
    const int gx = gx0 + tx * 4;
    const float* pb = pred + (size_t)b * CC * HWSZ + (size_t)gy * WW + gx;
    float4 X[CC];
#pragma unroll
    for (int c = 0; c < CC; c++) X[c] = __ldcs((const float4*)(pb + (size_t)c * HWSZ));

    // ---- row-B prefetch via cp.async (no destination registers) ----
#pragma unroll
    for (int c = 0; c < CC; c++) {
        unsigned sdst = (unsigned)__cvta_generic_to_shared(&s_pb[c][tid]);
        const float* gsrc = pb + (size_t)c * HWSZ + WW;
        asm volatile("cp.async.cg.shared.global [%0], [%1], 16;" :: "r"(sdst), "l"(gsrc));
    }
    asm volatile("cp.async.commit_group;" ::: "memory");

    // ---- stage target halo as packed bytes: int4 load + PRMT pack ----
    // uint j of halo row covers cols gx0-4+4j .. +3; OOB uint -> 0xFFFFFFFF
    {
        const int* tgt_b = target + b * HWSZ;
#pragma unroll
        for (int k = 0; k < 3; k++) {
            int idx = tid + k * 256;
            if (idx < HTOT) {
                int row = idx / HU;
                int j   = idx - row * HU;
                int gyy = gy0 + row - 2;
                int cb  = gx0 - 4 + 4 * j;
                unsigned u = 0xFFFFFFFFu;
                if (gyy >= 0 && gyy < HH && cb >= 0 && cb < WW) {
                    int4 w = *(const int4*)(tgt_b + gyy * WW + cb);   // 16B-aligned
                    unsigned lo = __byte_perm((unsigned)w.x, (unsigned)w.y, 0x4040);
                    unsigned hi = __byte_perm((unsigned)w.z, (unsigned)w.w, 0x4040);
                    u = __byte_perm(lo, hi, 0x5410);
                }
                s_t[idx] = u;
            }
        }
    }
    __syncthreads();

    // ---- SIMD byte morphology for 2 adjacent rows (shared vertical pair) ----
    unsigned dA, dB, tA, tB;
    {
        const int hb = (2 * ty) * HU + tx;
        unsigned h1a = s_t[hb + HU],     h1b = s_t[hb + HU + 1],     h1c = s_t[hb + HU + 2];
        unsigned h2a = s_t[hb + 2*HU],   h2b = s_t[hb + 2*HU + 1],   h2c = s_t[hb + 2*HU + 2];
        unsigned h3a = s_t[hb + 3*HU],   h3b = s_t[hb + 3*HU + 1],   h3c = s_t[hb + 3*HU + 2];
        unsigned h4a = s_t[hb + 4*HU],   h4b = s_t[hb + 4*HU + 1],   h4c = s_t[hb + 4*HU + 2];
        unsigned c0  = s_t[hb + 1];            // halo row r,   center uint
        unsigned c5  = s_t[hb + 5*HU + 1];     // halo row r+5, center uint

        unsigned pxa = __vmaxs4(h2a, h3a), pxb = __vmaxs4(h2b, h3b), pxc = __vmaxs4(h2c, h3c);
        unsigned qna = __vminu4(h2a, h3a), qnb = __vminu4(h2b, h3b), qnc = __vminu4(h2c, h3c);

        unsigned mxA = __vmaxs4(hwin_max(__vmaxs4(pxa, h1a), __vmaxs4(pxb, h1b), __vmaxs4(pxc, h1c)),
                                __vmaxs4(c0, h4b));
        unsigned mnA = __vminu4(hwin_min(__vminu4(qna, h1a), __vminu4(qnb, h1b), __vminu4(qnc, h1c)),
                                __vminu4(c0, h4b));
        unsigned mxB = __vmaxs4(hwin_max(__vmaxs4(pxa, h4a), __vmaxs4(pxb, h4b), __vmaxs4(pxc, h4c)),
                                __vmaxs4(h1b, c5));
        unsigned mnB = __vminu4(hwin_min(__vminu4(qna, h4a), __vminu4(qnb, h4b), __vminu4(qnc, h4c)),
                                __vminu4(h1b, c5));

        tA = h2b;  dA = mxA ^ mnA;
        tB = h3b;  dB = mxB ^ mnB;
    }

    float sump[CC], inter[CC];
    unsigned cntA = 0, cntB = 0;               // classes 0-3 / 4-7, 8-bit fields (max 8/thread)
#pragma unroll
    for (int c = 0; c < CC; c++) { sump[c] = 0.f; inter[c] = 0.f; }
    float cw_s = 0.f;                          // ce*(1+2w), w in {1,10} -> 3 or 21

    auto proc_row = [&](unsigned t_packed, unsigned d) {
#pragma unroll
        for (int p = 0; p < 4; p++) {
            const unsigned tp = __byte_perm(t_packed, 0u, 0x4440u | p);
            const unsigned db = __byte_perm(d, 0u, 0x4440u | p);

            // exp WITHOUT max-subtraction: inputs N(0,1), |x| < ~6, no overflow
            float e[CC];
#pragma unroll
            for (int c = 0; c < CC; c++) e[c] = __expf(CP(X[c], p));
            float se = ((e[0] + e[1]) + (e[2] + e[3])) + ((e[4] + e[5]) + (e[6] + e[7]));
            float inv = __fdividef(1.0f, se);

            float xt = CP(X[0], p);
#pragma unroll
            for (int c = 1; c < CC; c++) xt = (tp == (unsigned)c) ? CP(X[c], p) : xt;
            const float ce = __logf(se) - xt;

#pragma unroll
            for (int c = 0; c < CC; c++) {
                sump[c] = fmaf(e[c], inv, sump[c]);
                if (tp == (unsigned)c) inter[c] = fmaf(e[c], inv, inter[c]);
            }

            cw_s = fmaf(db ? 21.0f : 3.0f, ce, cw_s);

            unsigned inc = 1u << ((tp & 3u) * 8);
            cntA += (tp < 4u) ? inc : 0u;
            cntB += (tp < 4u) ? 0u : inc;
        }
    };

    proc_row(tA, dA);                          // row A (X already loaded)

    // row B: cp.async data is ready (each thread reads only its own chunks)
    asm volatile("cp.async.wait_group 0;" ::: "memory");
#pragma unroll
    for (int c = 0; c < CC; c++) X[c] = s_pb[c][tid];
    proc_row(tB, dB);

    // ---- block reduction: 3 shuffle levels (lanes 0-3 hold partials) ----
    const int lane = tid & 31;
    const int warp = tid >> 5;
    {
        float q[17];
#pragma unroll
        for (int c = 0; c < CC; c++) { q[c] = sump[c]; q[8 + c] = inter[c]; }
        q[16] = cw_s;
#pragma unroll
        for (int k = 0; k < 17; k++) {
            float v = q[k];
            v += __shfl_down_sync(0xFFFFFFFFu, v, 16);
            v += __shfl_down_sync(0xFFFFFFFFu, v, 8);
            v += __shfl_down_sync(0xFFFFFFFFu, v, 4);
            if (lane < 4) s_red[k][warp * 4 + lane] = v;
        }
        // counts: two 16-lane REDUX halves (8-bit fields, max 8*16=128, no overflow)
        unsigned ua, ub;
        if (lane < 16) {
            ua = __reduce_add_sync(0x0000FFFFu, cntA);
            ub = __reduce_add_sync(0x0000FFFFu, cntB);
        } else {
            ua = __reduce_add_sync(0xFFFF0000u, cntA);
            ub = __reduce_add_sync(0xFFFF0000u, cntB);
        }
        if ((lane & 15) == 0) {
            s_cnt[0][warp * 2 + (lane >> 4)] = ua;
            s_cnt[1][warp * 2 + (lane >> 4)] = ub;
        }
    }
    __syncthreads();

    if (tid < 17) {
        float s = 0.f;
#pragma unroll
        for (int w = 0; w < 32; w++) s += s_red[tid][w];
        int gi = (tid < 16) ? tid : 24;
        atomicAdd(&g_acc[b][gi], (double)s);
    }
    if (tid >= 32 && tid < 40) {
        int c = tid - 32;
        unsigned s = 0;
#pragma unroll
        for (int w = 0; w < 16; w++)
            s += (s_cnt[c >> 2][w] >> ((c & 3) * 8)) & 0xFFu;
        atomicAdd(&g_acc[b][16 + c], (double)s);
    }

    // ---- last-block finalize ----
    __syncthreads();
    if (tid == 0) {
        __threadfence();
        unsigned r = atomicAdd(&g_ticket, 1u);
        s_last = (r == NBLOCKS - 1);
        s_fin[0] = 0.f; s_fin[1] = 0.f;
    }
    __syncthreads();
    if (!s_last) return;
    __threadfence();

    float dterm = 0.f;
    if (tid < BB * CC) {
        int bb = tid >> 3, cc = tid & 7;
        float it   = (float)g_acc[bb][8 + cc];
        float card = (float)(g_acc[bb][cc] + g_acc[bb][16 + cc]);
        dterm = (2.0f * it + 1e-6f) / (card + 1e-6f);
    }
#pragma unroll
    for (int off = 16; off > 0; off >>= 1)
        dterm += __shfl_down_sync(0xFFFFFFFFu, dterm, off);
    if (lane == 0 && warp < 2) atomicAdd(&s_fin[0], dterm);
    if (tid < BB) atomicAdd(&s_fin[1], (float)g_acc[tid][24]);
    __syncthreads();

    if (tid == 0) {
        const float N = (float)BB * HH * WW;
        float dice = 1.0f - s_fin[0] / (float)(BB * CC);
        out[0] = s_fin[1] / N + 3.0f * dice;
    }
    if (tid < BB * 26) ((double*)g_acc)[tid] = 0.0;
    if (tid == 0) g_ticket = 0u;
}

extern "C" void kernel_launch(void* const* d_in, const int* in_sizes, int n_in,
                              void* d_out, int out_size)
{
    const float* pred   = (const float*)d_in[0];
    const int*   target = (const int*)d_in[1];
    float* out = (float*)d_out;

    dim3 block(BX, BY, 1);
    dim3 grid(WW / TW, HH / TH, BB);
    loss_main_kernel<<<grid, block>>>(pred, target, out);
}

// round 15
// speedup vs baseline: 1.4854x; 1.2960x over previous
#include <cuda_runtime.h>
#include <cuda_bf16.h>

// Fixed shapes
#define BB 8
#define CC 8
#define HH 512
#define WW 1024
#define HWSZ (HH * WW)

// Tiling: 32x8 threads; each thread owns 8 pixels = 2 adjacent rows x 4 cols
#define BX 32
#define BY 8
#define TW (BX * 4)        // tile width 128 px
#define TH 16              // tile height 16 px (2 rows per thread)
#define NWARPS 8
#define NBLOCKS ((WW / TW) * (HH / TH) * BB)   // 2048

#define HROWS (TH + 4)     // 20
#define HU 34              // uints per halo row (136 bytes: cols gx0-4 .. gx0+131)
#define HTOT (HROWS * HU)  // 680 uints

__device__ double g_acc[BB][26];   // zeroed at module load; last block re-zeroes
__device__ unsigned g_ticket;

#define CP(v, p) ((p) == 0 ? (v).x : (p) == 1 ? (v).y : (p) == 2 ? (v).z : (v).w)

__device__ __forceinline__ unsigned hwin_max(unsigned l, unsigned m, unsigned h) {
    return __vmaxs4(__vmaxs4(__byte_perm(l, m, 0x5432), __byte_perm(l, m, 0x6543)),
           __vmaxs4(m, __vmaxs4(__byte_perm(m, h, 0x4321), __byte_perm(m, h, 0x5432))));
}
__device__ __forceinline__ unsigned hwin_min(unsigned l, unsigned m, unsigned h) {
    return __vminu4(__vminu4(__byte_perm(l, m, 0x5432), __byte_perm(l, m, 0x6543)),
           __vminu4(m, __vminu4(__byte_perm(m, h, 0x4321), __byte_perm(m, h, 0x5432))));
}

__global__ __launch_bounds__(256, 4) void loss_main_kernel(
    const float* __restrict__ pred, const int* __restrict__ target,
    float* __restrict__ out)
{
    __shared__ __align__(16) unsigned s_t[HTOT];        // packed byte labels
    __shared__ float s_red[17][33];                     // padded (bank-conflict-free)
    __shared__ unsigned s_cnt[2][16];
    __shared__ float s_fin[2];
    __shared__ int s_last;

    const int b   = blockIdx.z;
    const int gx0 = blockIdx.x * TW;
    const int gy0 = blockIdx.y * TH;
    const int tx  = threadIdx.x;
    const int ty  = threadIdx.y;
    const int tid = ty * BX + tx;

    // ---- HOISTED row-A pred loads: 8 independent LDG.128 first; consumed
    //      after staging + sync + morphology (covers DRAM latency) ----
    const int gy = gy0 + 2 * ty;          // row A; row B = gy+1
    const int gx = gx0 + tx * 4;
    const float* pb = pred + (size_t)b * CC * HWSZ + (size_t)gy * WW + gx;
    float4 X[CC];
#pragma unroll
    for (int c = 0; c < CC; c++) X[c] = __ldcs((const float4*)(pb + (size_t)c * HWSZ));

    // ---- stage target halo as packed bytes: int4 load + PRMT pack ----
    // uint j of halo row covers cols gx0-4+4j .. +3; OOB uint -> 0xFFFFFFFF
    {
        const int* tgt_b = target + b * HWSZ;
#pragma unroll
        for (int k = 0; k < 3; k++) {
            int idx = tid + k * 256;
            if (idx < HTOT) {
                int row = idx / HU;
                int j   = idx - row * HU;
                int gyy = gy0 + row - 2;
                int cb  = gx0 - 4 + 4 * j;
                unsigned u = 0xFFFFFFFFu;
                if (gyy >= 0 && gyy < HH && cb >= 0 && cb < WW) {
                    int4 w = *(const int4*)(tgt_b + gyy * WW + cb);   // 16B-aligned
                    unsigned lo = __byte_perm((unsigned)w.x, (unsigned)w.y, 0x4040);
                    unsigned hi = __byte_perm((unsigned)w.z, (unsigned)w.w, 0x4040);
                    u = __byte_perm(lo, hi, 0x5410);
                }
                s_t[idx] = u;
            }
        }
    }
    __syncthreads();

    // ---- SIMD byte morphology for 2 adjacent rows (shared vertical pair) ----
    unsigned dA, dB, tA, tB;
    {
        const int hb = (2 * ty) * HU + tx;
        unsigned h1a = s_t[hb + HU],     h1b = s_t[hb + HU + 1],     h1c = s_t[hb + HU + 2];
        unsigned h2a = s_t[hb + 2*HU],   h2b = s_t[hb + 2*HU + 1],   h2c = s_t[hb + 2*HU + 2];
        unsigned h3a = s_t[hb + 3*HU],   h3b = s_t[hb + 3*HU + 1],   h3c = s_t[hb + 3*HU + 2];
        unsigned h4a = s_t[hb + 4*HU],   h4b = s_t[hb + 4*HU + 1],   h4c = s_t[hb + 4*HU + 2];
        unsigned c0  = s_t[hb + 1];            // halo row r,   center uint
        unsigned c5  = s_t[hb + 5*HU + 1];     // halo row r+5, center uint

        unsigned pxa = __vmaxs4(h2a, h3a), pxb = __vmaxs4(h2b, h3b), pxc = __vmaxs4(h2c, h3c);
        unsigned qna = __vminu4(h2a, h3a), qnb = __vminu4(h2b, h3b), qnc = __vminu4(h2c, h3c);

        unsigned mxA = __vmaxs4(hwin_max(__vmaxs4(pxa, h1a), __vmaxs4(pxb, h1b), __vmaxs4(pxc, h1c)),
                                __vmaxs4(c0, h4b));
        unsigned mnA = __vminu4(hwin_min(__vminu4(qna, h1a), __vminu4(qnb, h1b), __vminu4(qnc, h1c)),
                                __vminu4(c0, h4b));
        unsigned mxB = __vmaxs4(hwin_max(__vmaxs4(pxa, h4a), __vmaxs4(pxb, h4b), __vmaxs4(pxc, h4c)),
                                __vmaxs4(h1b, c5));
        unsigned mnB = __vminu4(hwin_min(__vminu4(qna, h4a), __vminu4(qnb, h4b), __vminu4(qnc, h4c)),
                                __vminu4(h1b, c5));

        tA = h2b;  dA = mxA ^ mnA;             // row A labels / boundary bytes
        tB = h3b;  dB = mxB ^ mnB;             // row B
    }

    float sump[CC], inter[CC];
    unsigned cntA = 0, cntB = 0;               // classes 0-3 / 4-7, 8-bit fields (max 8/thread)
#pragma unroll
    for (int c = 0; c < CC; c++) { sump[c] = 0.f; inter[c] = 0.f; }
    float cw_s = 0.f;                          // ce*(1+2w), w in {1,10} -> 3 or 21

    // process one pixel given its 8 channel logits
    auto proc_px = [&](const float* xc, unsigned tp, unsigned db) {
        // exp WITHOUT max-subtraction: inputs N(0,1), |x| < ~6, no overflow
        float e[CC];
#pragma unroll
        for (int c = 0; c < CC; c++) e[c] = __expf(xc[c]);
        float se = ((e[0] + e[1]) + (e[2] + e[3])) + ((e[4] + e[5]) + (e[6] + e[7]));
        float inv = __fdividef(1.0f, se);

        float xt = xc[0];
#pragma unroll
        for (int c = 1; c < CC; c++) xt = (tp == (unsigned)c) ? xc[c] : xt;
        const float ce = __logf(se) - xt;

#pragma unroll
        for (int c = 0; c < CC; c++) {
            sump[c] = fmaf(e[c], inv, sump[c]);
            if (tp == (unsigned)c) inter[c] = fmaf(e[c], inv, inter[c]);
        }

        cw_s = fmaf(db ? 21.0f : 3.0f, ce, cw_s);

        unsigned inc = 1u << ((tp & 3u) * 8);
        cntA += (tp < 4u) ? inc : 0u;
        cntB += (tp < 4u) ? 0u : inc;
    };

#define TPB(tv, p_) (__byte_perm((tv), 0u, 0x4440u | (p_)))
    float xq[CC];
#define EXTX(fld) do { xq[0]=X[0].fld; xq[1]=X[1].fld; xq[2]=X[2].fld; xq[3]=X[3].fld; \
                       xq[4]=X[4].fld; xq[5]=X[5].fld; xq[6]=X[6].fld; xq[7]=X[7].fld; } while(0)

    const float* pbB = pb + WW;   // row B base

    // row A px 0,1 (components .x,.y)
    EXTX(x); proc_px(xq, TPB(tA,0), TPB(dA,0));
    EXTX(y); proc_px(xq, TPB(tA,1), TPB(dA,1));

    // .x/.y now dead -> load row-B first halves into them (8 x LDG.64 in flight)
#pragma unroll
    for (int c = 0; c < CC; c++) {
        float2 v = __ldcs((const float2*)(pbB + (size_t)c * HWSZ));
        X[c].x = v.x; X[c].y = v.y;
    }

    // row A px 2,3 (components .z,.w) — covers row-B first-half latency
    EXTX(z); proc_px(xq, TPB(tA,2), TPB(dA,2));
    EXTX(w); proc_px(xq, TPB(tA,3), TPB(dA,3));

    // .z/.w now dead -> load row-B second halves
#pragma unroll
    for (int c = 0; c < CC; c++) {
        float2 v = __ldcs((const float2*)(pbB + (size_t)c * HWSZ + 2));
        X[c].z = v.x; X[c].w = v.y;
    }

    // row B px 0,1 (first halves, loaded 2 pixels ago)
    EXTX(x); proc_px(xq, TPB(tB,0), TPB(dB,0));
    EXTX(y); proc_px(xq, TPB(tB,1), TPB(dB,1));
    // row B px 2,3
    EXTX(z); proc_px(xq, TPB(tB,2), TPB(dB,2));
    EXTX(w); proc_px(xq, TPB(tB,3), TPB(dB,3));

    // ---- block reduction: 3 shuffle levels (lanes 0-3 hold partials) ----
    const int lane = tid & 31;
    const int warp = tid >> 5;
    {
        float q[17];
#pragma unroll
        for (int c = 0; c < CC; c++) { q[c] = sump[c]; q[8 + c] = inter[c]; }
        q[16] = cw_s;
#pragma unroll
        for (int k = 0; k < 17; k++) {
            float v = q[k];
            v += __shfl_down_sync(0xFFFFFFFFu, v, 16);
            v += __shfl_down_sync(0xFFFFFFFFu, v, 8);
            v += __shfl_down_sync(0xFFFFFFFFu, v, 4);
            if (lane < 4) s_red[k][warp * 4 + lane] = v;
        }
        // counts: two 16-lane REDUX halves (8-bit fields, max 8*16=128, no overflow)
        unsigned ua, ub;
        if (lane < 16) {
            ua = __reduce_add_sync(0x0000FFFFu, cntA);
            ub = __reduce_add_sync(0x0000FFFFu, cntB);
        } else {
            ua = __reduce_add_sync(0xFFFF0000u, cntA);
            ub = __reduce_add_sync(0xFFFF0000u, cntB);
        }
        if ((lane & 15) == 0) {
            s_cnt[0][warp * 2 + (lane >> 4)] = ua;
            s_cnt[1][warp * 2 + (lane >> 4)] = ub;
        }
    }
    __syncthreads();

    if (tid < 17) {
        float s = 0.f;
#pragma unroll
        for (int w = 0; w < 32; w++) s += s_red[tid][w];
        int gi = (tid < 16) ? tid : 24;
        atomicAdd(&g_acc[b][gi], (double)s);
    }
    if (tid >= 32 && tid < 40) {
        int c = tid - 32;
        unsigned s = 0;
#pragma unroll
        for (int w = 0; w < 16; w++)
            s += (s_cnt[c >> 2][w] >> ((c & 3) * 8)) & 0xFFu;
        atomicAdd(&g_acc[b][16 + c], (double)s);
    }

    // ---- last-block finalize ----
    __syncthreads();
    if (tid == 0) {
        __threadfence();
        unsigned r = atomicAdd(&g_ticket, 1u);
        s_last = (r == NBLOCKS - 1);
        s_fin[0] = 0.f; s_fin[1] = 0.f;
    }
    __syncthreads();
    if (!s_last) return;
    __threadfence();

    float dterm = 0.f;
    if (tid < BB * CC) {
        int bb = tid >> 3, cc = tid & 7;
        float it   = (float)g_acc[bb][8 + cc];
        float card = (float)(g_acc[bb][cc] + g_acc[bb][16 + cc]);
        dterm = (2.0f * it + 1e-6f) / (card + 1e-6f);
    }
#pragma unroll
    for (int off = 16; off > 0; off >>= 1)
        dterm += __shfl_down_sync(0xFFFFFFFFu, dterm, off);
    if (lane == 0 && warp < 2) atomicAdd(&s_fin[0], dterm);
    if (tid < BB) atomicAdd(&s_fin[1], (float)g_acc[tid][24]);
    __syncthreads();

    if (tid == 0) {
        const float N = (float)BB * HH * WW;
        float dice = 1.0f - s_fin[0] / (float)(BB * CC);
        out[0] = s_fin[1] / N + 3.0f * dice;
    }
    if (tid < BB * 26) ((double*)g_acc)[tid] = 0.0;
    if (tid == 0) g_ticket = 0u;
}

extern "C" void kernel_launch(void* const* d_in, const int* in_sizes, int n_in,
                              void* d_out, int out_size)
{
    const float* pred   = (const float*)d_in[0];
    const int*   target = (const int*)d_in[1];
    float* out = (float*)d_out;

    dim3 block(BX, BY, 1);
    dim3 grid(WW / TW, HH / TH, BB);
    loss_main_kernel<<<grid, block>>>(pred, target, out);
}